// round 9
// baseline (speedup 1.0000x reference)
#include <cuda_runtime.h>
#include <cuda_bf16.h>
#include <cstdint>

#define B_  8
#define S1_ 2048
#define S2_ 2048
#define D_  512
#define F_  256

#define NQKV (B_ * S1_ * F_)
#define NFEAT (B_ * S1_ * D_)

__device__ __align__(16) __nv_bfloat16 g_f1h[NFEAT];
__device__ __align__(16) __nv_bfloat16 g_f1l[NFEAT];
__device__ __align__(16) __nv_bfloat16 g_f2h[NFEAT];
__device__ __align__(16) __nv_bfloat16 g_f2l[NFEAT];
__device__ __align__(16) __nv_bfloat16 g_wq[2][D_ * F_];
__device__ __align__(16) __nv_bfloat16 g_wk[2][D_ * F_];
__device__ __align__(16) __nv_bfloat16 g_wv[2][D_ * F_];
__device__ __align__(16) __nv_bfloat16 g_wf[2][F_ * F_];
__device__ __align__(16) __nv_bfloat16 g_Qh [NQKV];
__device__ __align__(16) __nv_bfloat16 g_Ql [NQKV];
__device__ __align__(16) __nv_bfloat16 g_Kh [NQKV];
__device__ __align__(16) __nv_bfloat16 g_Kl [NQKV];
__device__ __align__(16) __nv_bfloat16 g_VTh[NQKV];   // [b, f, t]
__device__ __align__(16) __nv_bfloat16 g_VTl[NQKV];
__device__ __align__(16) __nv_bfloat16 g_AOh[NQKV];
__device__ __align__(16) __nv_bfloat16 g_AOl[NQKV];

// ---------------------------------------------------------------------------
__device__ __forceinline__ uint32_t smem_to_u32(const void* p) {
    uint32_t a;
    asm("{ .reg .u64 t; cvta.to.shared.u64 t, %1; cvt.u32.u64 %0, t; }"
        : "=r"(a) : "l"(p));
    return a;
}
__device__ __forceinline__ void ldsm4(uint32_t& r0, uint32_t& r1,
                                      uint32_t& r2, uint32_t& r3, uint32_t addr) {
    asm volatile("ldmatrix.sync.aligned.m8n8.x4.shared.b16 {%0,%1,%2,%3}, [%4];"
        : "=r"(r0), "=r"(r1), "=r"(r2), "=r"(r3) : "r"(addr));
}
__device__ __forceinline__ void mma_bf16(float (&d)[4], const uint32_t (&a)[4],
                                         uint32_t b0, uint32_t b1) {
    asm volatile(
        "mma.sync.aligned.m16n8k16.row.col.f32.bf16.bf16.f32 "
        "{%0,%1,%2,%3}, {%4,%5,%6,%7}, {%8,%9}, {%0,%1,%2,%3};"
        : "+f"(d[0]), "+f"(d[1]), "+f"(d[2]), "+f"(d[3])
        : "r"(a[0]), "r"(a[1]), "r"(a[2]), "r"(a[3]), "r"(b0), "r"(b1));
}
__device__ __forceinline__ void split_bf16(float x, __nv_bfloat16& h, __nv_bfloat16& l) {
    h = __float2bfloat16(x);
    l = __float2bfloat16(x - __bfloat162float(h));
}
__device__ __forceinline__ uint32_t pack2(__nv_bfloat16 a, __nv_bfloat16 b) {
    return (uint32_t)__bfloat16_as_ushort(a) | ((uint32_t)__bfloat16_as_ushort(b) << 16);
}
#define CP_ASYNC16(dst, src) \
    asm volatile("cp.async.cg.shared.global [%0], [%1], 16;" :: "r"(dst), "l"(src))
#define CP_COMMIT() asm volatile("cp.async.commit_group;" ::: "memory")
#define CP_WAIT0()  asm volatile("cp.async.wait_group 0;" ::: "memory")

// ---------------------------------------------------------------------------
__global__ void __launch_bounds__(256) split_f32_kernel(
    const float* __restrict__ in, __nv_bfloat16* __restrict__ h,
    __nv_bfloat16* __restrict__ l, int n4)
{
    int i = blockIdx.x * 256 + threadIdx.x;
    if (i >= n4) return;
    float4 v = ((const float4*)in)[i];
    __nv_bfloat16 h0,l0,h1,l1,h2,l2,h3,l3;
    split_bf16(v.x,h0,l0); split_bf16(v.y,h1,l1);
    split_bf16(v.z,h2,l2); split_bf16(v.w,h3,l3);
    ((uint2*)h)[i] = make_uint2(pack2(h0,h1), pack2(h2,h3));
    ((uint2*)l)[i] = make_uint2(pack2(l0,l1), pack2(l2,l3));
}

// All weights split + transpose in one launch.
__global__ void __launch_bounds__(256) split_weights_kernel(
    const float* __restrict__ Wq, const float* __restrict__ Wk,
    const float* __restrict__ Wv, const float* __restrict__ Wfc,
    __nv_bfloat16* __restrict__ wq0, __nv_bfloat16* __restrict__ wq1,
    __nv_bfloat16* __restrict__ wk0, __nv_bfloat16* __restrict__ wk1,
    __nv_bfloat16* __restrict__ wv0, __nv_bfloat16* __restrict__ wv1,
    __nv_bfloat16* __restrict__ wf0, __nv_bfloat16* __restrict__ wf1)
{
    int i = blockIdx.x * 256 + threadIdx.x;
    const int NW = D_ * F_;
    __nv_bfloat16 h, l;
    if (i < 3 * NW) {
        int which = i / NW, j = i - which * NW;
        int n = j / D_, k = j - n * D_;
        const float* W = which == 0 ? Wq : (which == 1 ? Wk : Wv);
        split_bf16(W[(size_t)k * F_ + n], h, l);
        __nv_bfloat16* Th = which == 0 ? wq0 : (which == 1 ? wk0 : wv0);
        __nv_bfloat16* Tl = which == 0 ? wq1 : (which == 1 ? wk1 : wv1);
        Th[j] = h; Tl[j] = l;
    } else {
        int j = i - 3 * NW;
        if (j >= F_ * F_) return;
        int n = j / F_, k = j - n * F_;
        split_bf16(Wfc[(size_t)k * F_ + n], h, l);
        wf0[j] = h; wf1[j] = l;
    }
}

// ---------------------------------------------------------------------------
// HMMA GEMM core (CTA 128x128, 8 warps 4mx2n, k-block 64, double-buffered).
// KDV threaded through both macros explicitly.
// ---------------------------------------------------------------------------
#define GEMM_SMEM 131072
#define GISSUE(buf, k0, KDV) do { \
    uint32_t gbase = smb + (buf) * 65536; \
    _Pragma("unroll") \
    for (int p = 0; p < 4; p++) { \
        int r = p * 32 + (tid >> 3); int c = tid & 7; \
        uint32_t d = r * 128 + (((uint32_t)(c ^ (r & 7))) << 4); \
        CP_ASYNC16(gbase + d,         Ah + (size_t)(m0 + r) * (KDV) + (k0) + c * 8); \
        CP_ASYNC16(gbase + 16384 + d, Al + (size_t)(m0 + r) * (KDV) + (k0) + c * 8); \
        CP_ASYNC16(gbase + 32768 + d, Bh + (size_t)(n0 + r) * (KDV) + (k0) + c * 8); \
        CP_ASYNC16(gbase + 49152 + d, Bl + (size_t)(n0 + r) * (KDV) + (k0) + c * 8); \
    } } while (0)

#define GEMM_BODY(KDV) \
    float acc[2][8][4]; \
    _Pragma("unroll") \
    for (int i = 0; i < 2; i++) \
        _Pragma("unroll") \
        for (int j = 0; j < 8; j++) \
            _Pragma("unroll") \
            for (int k = 0; k < 4; k++) acc[i][j][k] = 0.f; \
    const int T = (KDV) / 64; \
    GISSUE(0, 0, KDV); CP_COMMIT(); \
    for (int t = 0; t < T; t++) { \
        CP_WAIT0(); \
        __syncthreads(); \
        if (t + 1 < T) { GISSUE((t + 1) & 1, (t + 1) * 64, KDV); CP_COMMIT(); } \
        const int cur = t & 1; \
        uint32_t aH = smb + cur * 65536 + arow * 128; \
        uint32_t aL = aH + 16384; \
        uint32_t bB = smb + cur * 65536 + 32768 + (wn * 64 + brow) * 128; \
        _Pragma("unroll") \
        for (int ks = 0; ks < 4; ks++) { \
            uint32_t ac = ((uint32_t)((2 * ks + ah) ^ as)) << 4; \
            uint32_t aq[2][4], alr[2][4]; \
            ldsm4(aq[0][0], aq[0][1], aq[0][2], aq[0][3], aH + ac); \
            ldsm4(aq[1][0], aq[1][1], aq[1][2], aq[1][3], aH + 16 * 128 + ac); \
            ldsm4(alr[0][0], alr[0][1], alr[0][2], alr[0][3], aL + ac); \
            ldsm4(alr[1][0], alr[1][1], alr[1][2], alr[1][3], aL + 16 * 128 + ac); \
            uint32_t bc = ((uint32_t)((2 * ks + bh2) ^ bs)) << 4; \
            _Pragma("unroll") \
            for (int ni = 0; ni < 4; ni++) { \
                uint32_t bh4[4], bl4[4]; \
                ldsm4(bh4[0], bh4[1], bh4[2], bh4[3], bB + ni * 2048 + bc); \
                ldsm4(bl4[0], bl4[1], bl4[2], bl4[3], bB + 16384 + ni * 2048 + bc); \
                _Pragma("unroll") \
                for (int mi = 0; mi < 2; mi++) { \
                    mma_bf16(acc[mi][2*ni],   aq[mi],  bh4[0], bh4[1]); \
                    mma_bf16(acc[mi][2*ni],   aq[mi],  bl4[0], bl4[1]); \
                    mma_bf16(acc[mi][2*ni],   alr[mi], bh4[0], bh4[1]); \
                    mma_bf16(acc[mi][2*ni+1], aq[mi],  bh4[2], bh4[3]); \
                    mma_bf16(acc[mi][2*ni+1], aq[mi],  bl4[2], bl4[3]); \
                    mma_bf16(acc[mi][2*ni+1], alr[mi], bh4[2], bh4[3]); \
                } \
            } \
        } \
        __syncthreads(); \
    }

// Fused Q/K/V projection GEMM: blockIdx.z selects product.
__global__ void __launch_bounds__(256, 1) gemm_qkv(
    const __nv_bfloat16* __restrict__ f1h, const __nv_bfloat16* __restrict__ f1l,
    const __nv_bfloat16* __restrict__ f2h, const __nv_bfloat16* __restrict__ f2l,
    const __nv_bfloat16* __restrict__ wqh, const __nv_bfloat16* __restrict__ wql,
    const __nv_bfloat16* __restrict__ wkh, const __nv_bfloat16* __restrict__ wkl,
    const __nv_bfloat16* __restrict__ wvh, const __nv_bfloat16* __restrict__ wvl,
    const float* __restrict__ bq, const float* __restrict__ bk,
    const float* __restrict__ bv,
    __nv_bfloat16* __restrict__ Qh, __nv_bfloat16* __restrict__ Ql,
    __nv_bfloat16* __restrict__ Kh, __nv_bfloat16* __restrict__ Kl,
    __nv_bfloat16* __restrict__ VTh, __nv_bfloat16* __restrict__ VTl)
{
    extern __shared__ char sm[];
    const uint32_t smb = smem_to_u32(sm);
    const int tid  = threadIdx.x;
    const int lane = tid & 31;
    const int wid  = tid >> 5;
    const int wm = wid & 3, wn = wid >> 2;
    const int n0 = blockIdx.x * 128, m0 = blockIdx.y * 128;
    const int z  = blockIdx.z;

    const __nv_bfloat16* Ah = z == 0 ? f1h : f2h;
    const __nv_bfloat16* Al = z == 0 ? f1l : f2l;
    const __nv_bfloat16* Bh = z == 0 ? wqh : (z == 1 ? wkh : wvh);
    const __nv_bfloat16* Bl = z == 0 ? wql : (z == 1 ? wkl : wvl);
    const float* bias = z == 0 ? bq : (z == 1 ? bk : bv);
    __nv_bfloat16* Oh = z == 0 ? Qh : (z == 1 ? Kh : VTh);
    __nv_bfloat16* Ol = z == 0 ? Ql : (z == 1 ? Kl : VTl);

    const int arow = wm * 32 + (lane & 15);
    const int as   = arow & 7;
    const int ah   = lane >> 4;
    const int brow = ((lane >> 4) << 3) + (lane & 7);
    const int bs   = lane & 7;
    const int bh2  = (lane >> 3) & 1;

    GEMM_BODY(D_)

    const int lq = lane & 3;
    #pragma unroll
    for (int mi = 0; mi < 2; mi++) {
        int r0 = m0 + wm * 32 + mi * 16 + (lane >> 2);
        int r1 = r0 + 8;
        #pragma unroll
        for (int nt = 0; nt < 8; nt++) {
            int col = n0 + wn * 64 + nt * 8 + 2 * lq;
            float b0 = bias[col], b1 = bias[col + 1];
            float v0 = acc[mi][nt][0] + b0, v1 = acc[mi][nt][1] + b1;
            float v2 = acc[mi][nt][2] + b0, v3 = acc[mi][nt][3] + b1;
            __nv_bfloat16 h0,l0,h1,l1,h2,l2,h3,l3;
            split_bf16(v0,h0,l0); split_bf16(v1,h1,l1);
            split_bf16(v2,h2,l2); split_bf16(v3,h3,l3);
            if (z < 2) {
                size_t o0 = (size_t)r0 * 256 + col, o1 = (size_t)r1 * 256 + col;
                *(uint32_t*)(Oh + o0) = pack2(h0, h1);
                *(uint32_t*)(Ol + o0) = pack2(l0, l1);
                *(uint32_t*)(Oh + o1) = pack2(h2, h3);
                *(uint32_t*)(Ol + o1) = pack2(l2, l3);
            } else {
                size_t o0 = (size_t)(r0 >> 11) * (F_ * S2_) + (size_t)col * S2_ + (r0 & 2047);
                size_t o1 = (size_t)(r1 >> 11) * (F_ * S2_) + (size_t)col * S2_ + (r1 & 2047);
                Oh[o0] = h0; Oh[o0 + S2_] = h1; Ol[o0] = l0; Ol[o0 + S2_] = l1;
                Oh[o1] = h2; Oh[o1 + S2_] = h3; Ol[o1] = l2; Ol[o1 + S2_] = l3;
            }
        }
    }
}

// FC GEMM (fp32 output to d_out)
__global__ void __launch_bounds__(256, 1) gemm_fc(
    const __nv_bfloat16* __restrict__ Ah, const __nv_bfloat16* __restrict__ Al,
    const __nv_bfloat16* __restrict__ Bh, const __nv_bfloat16* __restrict__ Bl,
    const float* __restrict__ bias, float* __restrict__ Cf)
{
    extern __shared__ char sm[];
    const uint32_t smb = smem_to_u32(sm);
    const int tid  = threadIdx.x;
    const int lane = tid & 31;
    const int wid  = tid >> 5;
    const int wm = wid & 3, wn = wid >> 2;
    const int n0 = blockIdx.x * 128, m0 = blockIdx.y * 128;

    const int arow = wm * 32 + (lane & 15);
    const int as   = arow & 7;
    const int ah   = lane >> 4;
    const int brow = ((lane >> 4) << 3) + (lane & 7);
    const int bs   = lane & 7;
    const int bh2  = (lane >> 3) & 1;

    GEMM_BODY(F_)

    const int lq = lane & 3;
    #pragma unroll
    for (int mi = 0; mi < 2; mi++) {
        int r0 = m0 + wm * 32 + mi * 16 + (lane >> 2);
        int r1 = r0 + 8;
        #pragma unroll
        for (int nt = 0; nt < 8; nt++) {
            int col = n0 + wn * 64 + nt * 8 + 2 * lq;
            float b0 = bias[col], b1 = bias[col + 1];
            *(float2*)(Cf + (size_t)r0 * 256 + col) =
                make_float2(acc[mi][nt][0] + b0, acc[mi][nt][1] + b1);
            *(float2*)(Cf + (size_t)r1 * 256 + col) =
                make_float2(acc[mi][nt][2] + b0, acc[mi][nt][3] + b1);
        }
    }
}

// ---------------------------------------------------------------------------
// HMMA flash attention v3: 512 threads (16 warps = 8 qg x 2 kh), BQA=128,
// BKA=32 double-buffered cp.async, Qh fragments in registers (gmem direct),
// Ql in smem, Ph|Pl packed in one 128B row. No online max. Split-bf16 out.
// SMEM: QL 0(64K) | buf b @64K+64K*b: KH(16K) KL(16K) V(32K hi|lo)
//       P 192K(16K: hi ch0-3, lo ch4-7) LSM 208K(1K).
// ---------------------------------------------------------------------------
#define BQA 128
#define BKA 32
#define NKT (S2_ / BKA)
#define AQL 0
#define AKH(b) (65536 + (b) * 65536)
#define AKL(b) (81920 + (b) * 65536)
#define AV(b)  (98304 + (b) * 65536)
#define APS 196608
#define ALS 212992
#define ATTN_SMEM (212992 + 1024)

#define AISSUE(buf, kt) do { \
    _Pragma("unroll") \
    for (int p = 0; p < 2; p++) { \
        int id = p * 512 + tid; int r = id >> 5, c = id & 31; \
        uint32_t d = r * 512 + (((uint32_t)(c ^ (r & 7))) << 4); \
        CP_ASYNC16(smb + AKH(buf) + d, Khb + (size_t)((kt) + r) * F_ + c * 8); \
        CP_ASYNC16(smb + AKL(buf) + d, Klb + (size_t)((kt) + r) * F_ + c * 8); \
    } \
    _Pragma("unroll") \
    for (int p = 0; p < 4; p++) { \
        int id = p * 512 + tid; int r = id >> 3, c = id & 7; \
        const __nv_bfloat16* src = (c < 4) \
            ? (Vhb + (size_t)r * S2_ + (kt) + c * 8) \
            : (Vlb + (size_t)r * S2_ + (kt) + (c - 4) * 8); \
        CP_ASYNC16(smb + AV(buf) + r * 128 + (((uint32_t)(c ^ (r & 7))) << 4), src); \
    } } while (0)

__global__ void __launch_bounds__(512, 1) attn_kernel(
    const __nv_bfloat16* __restrict__ Qh, const __nv_bfloat16* __restrict__ Ql,
    const __nv_bfloat16* __restrict__ Kh, const __nv_bfloat16* __restrict__ Kl,
    const __nv_bfloat16* __restrict__ VTh, const __nv_bfloat16* __restrict__ VTl,
    __nv_bfloat16* __restrict__ AOh, __nv_bfloat16* __restrict__ AOl)
{
    extern __shared__ char sm[];
    const uint32_t smb = smem_to_u32(sm);
    const int tid  = threadIdx.x;
    const int wid  = tid >> 5;
    const int lane = tid & 31;
    const int b    = blockIdx.y;
    const int q0   = blockIdx.x * BQA;
    const int qg   = wid >> 1;      // 0..7 : 16 query rows each
    const int kh   = wid & 1;       // S: key half; PV: f half

    const __nv_bfloat16* Khb = Kh  + (size_t)b * S2_ * F_;
    const __nv_bfloat16* Klb = Kl  + (size_t)b * S2_ * F_;
    const __nv_bfloat16* Vhb = VTh + (size_t)b * F_ * S2_;
    const __nv_bfloat16* Vlb = VTl + (size_t)b * F_ * S2_;
    const __nv_bfloat16* Qlb = Ql  + ((size_t)(b * S1_ + q0)) * F_;
    const __nv_bfloat16* Qhb = Qh  + ((size_t)(b * S1_ + q0)) * F_;

    // issue Ql tile + first K/V buffer
    AISSUE(0, 0);
    #pragma unroll
    for (int p = 0; p < 8; p++) {
        int id = p * 512 + tid;
        int r = id >> 5, c = id & 31;
        uint32_t d = r * 512 + (((uint32_t)(c ^ (r & 7))) << 4);
        CP_ASYNC16(smb + AQL + d, Qlb + (size_t)r * F_ + c * 8);
    }
    CP_COMMIT();

    // Qh A-fragments loaded directly from gmem into registers (once)
    const int fr0 = qg * 16 + (lane >> 2);
    const int fcc = (lane & 3) * 2;
    uint32_t qf[16][4];
    #pragma unroll
    for (int ks = 0; ks < 16; ks++) {
        qf[ks][0] = *(const uint32_t*)(Qhb + (size_t)fr0 * F_ + 16 * ks + fcc);
        qf[ks][1] = *(const uint32_t*)(Qhb + (size_t)(fr0 + 8) * F_ + 16 * ks + fcc);
        qf[ks][2] = *(const uint32_t*)(Qhb + (size_t)fr0 * F_ + 16 * ks + 8 + fcc);
        qf[ks][3] = *(const uint32_t*)(Qhb + (size_t)(fr0 + 8) * F_ + 16 * ks + 8 + fcc);
    }

    const int arow = qg * 16 + (lane & 15);
    const int as   = arow & 7;
    const int ah   = lane >> 4;
    const uint32_t qlB = smb + AQL + arow * 512;
    const uint32_t pB  = smb + APS + arow * 128;
    const int brow = ((lane >> 4) << 3) + (lane & 7);
    const int bs   = lane & 7;
    const int bh2  = (lane >> 3) & 1;
    const int crow = qg * 16 + (lane >> 2);
    const int lq   = lane & 3;

    float accO[16][4];
    #pragma unroll
    for (int i = 0; i < 16; i++)
        #pragma unroll
        for (int j = 0; j < 4; j++) accO[i][j] = 0.f;
    float lsum0 = 0.f, lsum1 = 0.f;
    const float scale = 0.0625f;

    for (int it = 0; it < NKT; it++) {
        const int cur = it & 1;
        CP_WAIT0();
        __syncthreads();
        if (it + 1 < NKT) { AISSUE(cur ^ 1, (it + 1) * BKA); CP_COMMIT(); }

        // ---- S = Qh@Kh + Qh@Kl + Ql@Kh : warp 16q x 16k ----
        float sa[2][4];
        #pragma unroll
        for (int j = 0; j < 4; j++) { sa[0][j] = 0.f; sa[1][j] = 0.f; }
        const uint32_t kbH = smb + AKH(cur) + (kh * 16 + brow) * 512;
        const uint32_t kbL = smb + AKL(cur) + (kh * 16 + brow) * 512;
        #pragma unroll
        for (int ks = 0; ks < 16; ks++) {
            uint32_t al4[4], bh4[4], bl4[4];
            uint32_t qc = ((uint32_t)((2 * ks + ah) ^ as)) << 4;
            ldsm4(al4[0], al4[1], al4[2], al4[3], qlB + qc);
            uint32_t kc = ((uint32_t)((2 * ks + bh2) ^ bs)) << 4;
            ldsm4(bh4[0], bh4[1], bh4[2], bh4[3], kbH + kc);
            ldsm4(bl4[0], bl4[1], bl4[2], bl4[3], kbL + kc);
            mma_bf16(sa[0], qf[ks], bh4[0], bh4[1]);
            mma_bf16(sa[0], qf[ks], bl4[0], bl4[1]);
            mma_bf16(sa[0], al4,    bh4[0], bh4[1]);
            mma_bf16(sa[1], qf[ks], bh4[2], bh4[3]);
            mma_bf16(sa[1], qf[ks], bl4[2], bl4[3]);
            mma_bf16(sa[1], al4,    bh4[2], bh4[3]);
        }

        // ---- softmax (no max-sub), split, store P (hi ch0-3 / lo ch4-7) ----
        {
            const int rA = crow, rB = crow + 8;
            #pragma unroll
            for (int nt = 0; nt < 2; nt++) {
                float p0 = __expf(sa[nt][0] * scale);
                float p1 = __expf(sa[nt][1] * scale);
                float p2 = __expf(sa[nt][2] * scale);
                float p3 = __expf(sa[nt][3] * scale);
                lsum0 += p0 + p1;
                lsum1 += p2 + p3;
                int hc = kh * 2 + nt;       // hi chunk 0..3
                uint32_t hA = (uint32_t)(rA * 128 + ((hc ^ (rA & 7)) << 4) + lq * 4);
                uint32_t hB = (uint32_t)(rB * 128 + ((hc ^ (rB & 7)) << 4) + lq * 4);
                uint32_t lA = (uint32_t)(rA * 128 + (((hc + 4) ^ (rA & 7)) << 4) + lq * 4);
                uint32_t lB = (uint32_t)(rB * 128 + (((hc + 4) ^ (rB & 7)) << 4) + lq * 4);
                __nv_bfloat16 h0,l0,h1,l1,h2,l2,h3,l3;
                split_bf16(p0,h0,l0); split_bf16(p1,h1,l1);
                split_bf16(p2,h2,l2); split_bf16(p3,h3,l3);
                *(uint32_t*)(sm + APS + hA) = pack2(h0, h1);
                *(uint32_t*)(sm + APS + hB) = pack2(h2, h3);
                *(uint32_t*)(sm + APS + lA) = pack2(l0, l1);
                *(uint32_t*)(sm + APS + lB) = pack2(l2, l3);
            }
        }
        __syncthreads();

        // ---- O += Ph@Vh + Ph@Vl + Pl@Vh : warp 16q x 128f ----
        {
            uint32_t pf[2][4], plf[2][4];
            #pragma unroll
            for (int ks = 0; ks < 2; ks++) {
                uint32_t hc = (uint32_t)(2 * ks + ah);
                ldsm4(pf[ks][0], pf[ks][1], pf[ks][2], pf[ks][3],
                      pB + ((hc ^ (uint32_t)as) << 4));
                ldsm4(plf[ks][0], plf[ks][1], plf[ks][2], plf[ks][3],
                      pB + (((hc + 4) ^ (uint32_t)as) << 4));
            }
            const uint32_t vb = smb + AV(cur) + (kh * 128 + brow) * 128;
            #pragma unroll
            for (int np = 0; np < 8; np++) {
                #pragma unroll
                for (int ks = 0; ks < 2; ks++) {
                    uint32_t vh4[4], vl4[4];
                    uint32_t ch = (uint32_t)(2 * ks + bh2);
                    uint32_t base = vb + np * 16 * 128;
                    ldsm4(vh4[0], vh4[1], vh4[2], vh4[3],
                          base + ((ch ^ (uint32_t)bs) << 4));
                    ldsm4(vl4[0], vl4[1], vl4[2], vl4[3],
                          base + (((ch + 4) ^ (uint32_t)bs) << 4));
                    const int n0 = np * 2, n1 = np * 2 + 1;
                    mma_bf16(accO[n0], pf[ks],  vh4[0], vh4[1]);
                    mma_bf16(accO[n0], pf[ks],  vl4[0], vl4[1]);
                    mma_bf16(accO[n0], plf[ks], vh4[0], vh4[1]);
                    mma_bf16(accO[n1], pf[ks],  vh4[2], vh4[3]);
                    mma_bf16(accO[n1], pf[ks],  vl4[2], vl4[3]);
                    mma_bf16(accO[n1], plf[ks], vh4[2], vh4[3]);
                }
            }
        }
    }

    // ---- reduce l across kh pairs, normalize, split-bf16 output ----
    float* lsm = (float*)(sm + ALS);
    lsum0 += __shfl_xor_sync(0xffffffffu, lsum0, 1);
    lsum0 += __shfl_xor_sync(0xffffffffu, lsum0, 2);
    lsum1 += __shfl_xor_sync(0xffffffffu, lsum1, 1);
    lsum1 += __shfl_xor_sync(0xffffffffu, lsum1, 2);
    __syncthreads();
    if (lq == 0) {
        lsm[kh * 128 + crow]     = lsum0;
        lsm[kh * 128 + crow + 8] = lsum1;
    }
    __syncthreads();

    const float inv0 = 1.f / (lsm[crow]     + lsm[128 + crow]);
    const float inv1 = 1.f / (lsm[crow + 8] + lsm[128 + crow + 8]);
    const size_t base0 = ((size_t)(b * S1_ + q0 + crow)) * F_;
    const size_t base1 = ((size_t)(b * S1_ + q0 + crow + 8)) * F_;
    #pragma unroll
    for (int nt = 0; nt < 16; nt++) {
        int col = kh * 128 + nt * 8 + 2 * lq;
        __nv_bfloat16 h0,l0,h1,l1,h2,l2,h3,l3;
        split_bf16(accO[nt][0] * inv0, h0, l0);
        split_bf16(accO[nt][1] * inv0, h1, l1);
        split_bf16(accO[nt][2] * inv1, h2, l2);
        split_bf16(accO[nt][3] * inv1, h3, l3);
        *(uint32_t*)(AOh + base0 + col) = pack2(h0, h1);
        *(uint32_t*)(AOl + base0 + col) = pack2(l0, l1);
        *(uint32_t*)(AOh + base1 + col) = pack2(h2, h3);
        *(uint32_t*)(AOl + base1 + col) = pack2(l2, l3);
    }
}

// ---------------------------------------------------------------------------
extern "C" void kernel_launch(void* const* d_in, const int* in_sizes, int n_in,
                              void* d_out, int out_size)
{
    const float* feat1 = (const float*)d_in[0];
    const float* feat2 = (const float*)d_in[1];
    const float* Wq    = (const float*)d_in[2];
    const float* bq    = (const float*)d_in[3];
    const float* Wk    = (const float*)d_in[4];
    const float* bk    = (const float*)d_in[5];
    const float* Wv    = (const float*)d_in[6];
    const float* bv    = (const float*)d_in[7];
    const float* Wfc   = (const float*)d_in[8];
    const float* bfc   = (const float*)d_in[9];
    float* out = (float*)d_out;

    __nv_bfloat16 *f1h, *f1l, *f2h, *f2l, *Qh, *Ql, *Kh, *Kl, *VTh, *VTl, *AOh, *AOl;
    __nv_bfloat16 (*wq)[D_ * F_]; __nv_bfloat16 (*wk)[D_ * F_];
    __nv_bfloat16 (*wv)[D_ * F_]; __nv_bfloat16 (*wf)[F_ * F_];
    cudaGetSymbolAddress((void**)&f1h, g_f1h);
    cudaGetSymbolAddress((void**)&f1l, g_f1l);
    cudaGetSymbolAddress((void**)&f2h, g_f2h);
    cudaGetSymbolAddress((void**)&f2l, g_f2l);
    cudaGetSymbolAddress((void**)&wq,  g_wq);
    cudaGetSymbolAddress((void**)&wk,  g_wk);
    cudaGetSymbolAddress((void**)&wv,  g_wv);
    cudaGetSymbolAddress((void**)&wf,  g_wf);
    cudaGetSymbolAddress((void**)&Qh,  g_Qh);
    cudaGetSymbolAddress((void**)&Ql,  g_Ql);
    cudaGetSymbolAddress((void**)&Kh,  g_Kh);
    cudaGetSymbolAddress((void**)&Kl,  g_Kl);
    cudaGetSymbolAddress((void**)&VTh, g_VTh);
    cudaGetSymbolAddress((void**)&VTl, g_VTl);
    cudaGetSymbolAddress((void**)&AOh, g_AOh);
    cudaGetSymbolAddress((void**)&AOl, g_AOl);

    split_f32_kernel<<<NFEAT / 4 / 256, 256>>>(feat1, f1h, f1l, NFEAT / 4);
    split_f32_kernel<<<NFEAT / 4 / 256, 256>>>(feat2, f2h, f2l, NFEAT / 4);
    split_weights_kernel<<<(3 * D_ * F_ + F_ * F_ + 255) / 256, 256>>>(
        Wq, Wk, Wv, Wfc, wq[0], wq[1], wk[0], wk[1], wv[0], wv[1], wf[0], wf[1]);

    cudaFuncSetAttribute(gemm_qkv, cudaFuncAttributeMaxDynamicSharedMemorySize, GEMM_SMEM);
    cudaFuncSetAttribute(gemm_fc,  cudaFuncAttributeMaxDynamicSharedMemorySize, GEMM_SMEM);
    cudaFuncSetAttribute(attn_kernel, cudaFuncAttributeMaxDynamicSharedMemorySize, ATTN_SMEM);

    dim3 gq(2, B_ * S1_ / 128, 3);   // fused Q/K/V
    gemm_qkv<<<gq, 256, GEMM_SMEM>>>(f1h, f1l, f2h, f2l,
                                     wq[0], wq[1], wk[0], wk[1], wv[0], wv[1],
                                     bq, bk, bv, Qh, Ql, Kh, Kl, VTh, VTl);

    dim3 ag(S1_ / BQA, B_);          // (16, 8) — single wave
    attn_kernel<<<ag, 512, ATTN_SMEM>>>(Qh, Ql, Kh, Kl, VTh, VTl, AOh, AOl);

    dim3 gg(2, B_ * S1_ / 128);
    gemm_fc<<<gg, 256, GEMM_SMEM>>>(AOh, AOl, wf[0], wf[1], bfc, out);
}

// round 10
// speedup vs baseline: 1.5068x; 1.5068x over previous
#include <cuda_runtime.h>
#include <cuda_bf16.h>
#include <cstdint>

#define B_  8
#define S1_ 2048
#define S2_ 2048
#define D_  512
#define F_  256
#define NQKV (B_ * S1_ * F_)
#define NFEAT (B_ * S1_ * D_)

__device__ __align__(16) __nv_bfloat16 g_f1h[NFEAT];
__device__ __align__(16) __nv_bfloat16 g_f1l[NFEAT];
__device__ __align__(16) __nv_bfloat16 g_f2h[NFEAT];
__device__ __align__(16) __nv_bfloat16 g_f2l[NFEAT];
__device__ __align__(16) __nv_bfloat16 g_wq[2][D_ * F_];
__device__ __align__(16) __nv_bfloat16 g_wk[2][D_ * F_];
__device__ __align__(16) __nv_bfloat16 g_wv[2][D_ * F_];
__device__ __align__(16) __nv_bfloat16 g_wf[2][F_ * F_];
__device__ __align__(16) __nv_bfloat16 g_Qh [NQKV];
__device__ __align__(16) __nv_bfloat16 g_Ql [NQKV];
__device__ __align__(16) __nv_bfloat16 g_Kh [NQKV];
__device__ __align__(16) __nv_bfloat16 g_Kl [NQKV];
__device__ __align__(16) __nv_bfloat16 g_VTh[NQKV];
__device__ __align__(16) __nv_bfloat16 g_VTl[NQKV];
__device__ __align__(16) __nv_bfloat16 g_AOh[NQKV];
__device__ __align__(16) __nv_bfloat16 g_AOl[NQKV];

__device__ __forceinline__ uint32_t smem_to_u32(const void* p) {
    uint32_t a;
    asm("{ .reg .u64 t; cvta.to.shared.u64 t, %1; cvt.u32.u64 %0, t; }" : "=r"(a) : "l"(p));
    return a;
}
__device__ __forceinline__ void ldsm4(uint32_t& r0, uint32_t& r1, uint32_t& r2, uint32_t& r3, uint32_t a) {
    asm volatile("ldmatrix.sync.aligned.m8n8.x4.shared.b16 {%0,%1,%2,%3}, [%4];"
        : "=r"(r0), "=r"(r1), "=r"(r2), "=r"(r3) : "r"(a));
}
__device__ __forceinline__ void mma_bf16(float (&d)[4], const uint32_t* a, uint32_t b0, uint32_t b1) {
    asm volatile("mma.sync.aligned.m16n8k16.row.col.f32.bf16.bf16.f32 "
        "{%0,%1,%2,%3}, {%4,%5,%6,%7}, {%8,%9}, {%0,%1,%2,%3};"
        : "+f"(d[0]), "+f"(d[1]), "+f"(d[2]), "+f"(d[3])
        : "r"(a[0]), "r"(a[1]), "r"(a[2]), "r"(a[3]), "r"(b0), "r"(b1));
}
__device__ __forceinline__ void split_bf16(float x, __nv_bfloat16& h, __nv_bfloat16& l) {
    h = __float2bfloat16(x);
    l = __float2bfloat16(x - __bfloat162float(h));
}
__device__ __forceinline__ uint32_t pack2(__nv_bfloat16 a, __nv_bfloat16 b) {
    return (uint32_t)__bfloat16_as_ushort(a) | ((uint32_t)__bfloat16_as_ushort(b) << 16);
}
#define CP_ASYNC16(dst, src) asm volatile("cp.async.cg.shared.global [%0], [%1], 16;" :: "r"(dst), "l"(src))
#define CP_COMMIT() asm volatile("cp.async.commit_group;" ::: "memory")
#define CP_WAIT0()  asm volatile("cp.async.wait_group 0;" ::: "memory")

__global__ void __launch_bounds__(256) split_f32_kernel(
    const float* __restrict__ in, __nv_bfloat16* __restrict__ h,
    __nv_bfloat16* __restrict__ l, int n4)
{
    int i = blockIdx.x * 256 + threadIdx.x;
    if (i >= n4) return;
    float4 v = ((const float4*)in)[i];
    __nv_bfloat16 h0,l0,h1,l1,h2,l2,h3,l3;
    split_bf16(v.x,h0,l0); split_bf16(v.y,h1,l1);
    split_bf16(v.z,h2,l2); split_bf16(v.w,h3,l3);
    ((uint2*)h)[i] = make_uint2(pack2(h0,h1), pack2(h2,h3));
    ((uint2*)l)[i] = make_uint2(pack2(l0,l1), pack2(l2,l3));
}

__global__ void __launch_bounds__(256) split_weights_kernel(
    const float* __restrict__ Wq, const float* __restrict__ Wk,
    const float* __restrict__ Wv, const float* __restrict__ Wfc,
    __nv_bfloat16* __restrict__ wq0, __nv_bfloat16* __restrict__ wq1,
    __nv_bfloat16* __restrict__ wk0, __nv_bfloat16* __restrict__ wk1,
    __nv_bfloat16* __restrict__ wv0, __nv_bfloat16* __restrict__ wv1,
    __nv_bfloat16* __restrict__ wf0, __nv_bfloat16* __restrict__ wf1)
{
    int i = blockIdx.x * 256 + threadIdx.x;
    const int NW = D_ * F_;
    __nv_bfloat16 h, l;
    if (i < 3 * NW) {
        int which = i / NW, j = i - which * NW;
        int n = j / D_, k = j - n * D_;
        const float* W = which == 0 ? Wq : (which == 1 ? Wk : Wv);
        split_bf16(W[(size_t)k * F_ + n], h, l);
        __nv_bfloat16* Th = which == 0 ? wq0 : (which == 1 ? wk0 : wv0);
        __nv_bfloat16* Tl = which == 0 ? wq1 : (which == 1 ? wk1 : wv1);
        Th[j] = h; Tl[j] = l;
    } else {
        int j = i - 3 * NW;
        if (j >= F_ * F_) return;
        int n = j / F_, k = j - n * F_;
        split_bf16(Wfc[(size_t)k * F_ + n], h, l);
        wf0[j] = h; wf1[j] = l;
    }
}

// HMMA GEMM core: CTA 128x128, 8 warps, k-block 64, double-buffered.
// Batched ldsm: all 20 ldsm of a k-step issued before its 48 mma.
#define GEMM_SMEM 131072
#define GISSUE(buf, k0, KDV) do { \
    uint32_t gbase = smb + (buf) * 65536; \
    _Pragma("unroll") \
    for (int p = 0; p < 4; p++) { \
        int r = p * 32 + (tid >> 3); int c = tid & 7; \
        uint32_t d = r * 128 + (((uint32_t)(c ^ (r & 7))) << 4); \
        CP_ASYNC16(gbase + d,         Ah + (size_t)(m0 + r) * (KDV) + (k0) + c * 8); \
        CP_ASYNC16(gbase + 16384 + d, Al + (size_t)(m0 + r) * (KDV) + (k0) + c * 8); \
        CP_ASYNC16(gbase + 32768 + d, Bh + (size_t)(n0 + r) * (KDV) + (k0) + c * 8); \
        CP_ASYNC16(gbase + 49152 + d, Bl + (size_t)(n0 + r) * (KDV) + (k0) + c * 8); \
    } } while (0)

#define GEMM_BODY(KDV) \
    float acc[2][8][4]; \
    _Pragma("unroll") \
    for (int i = 0; i < 2; i++) \
        _Pragma("unroll") \
        for (int j = 0; j < 8; j++) \
            _Pragma("unroll") \
            for (int k = 0; k < 4; k++) acc[i][j][k] = 0.f; \
    const int T = (KDV) / 64; \
    GISSUE(0, 0, KDV); CP_COMMIT(); \
    for (int t = 0; t < T; t++) { \
        CP_WAIT0(); \
        __syncthreads(); \
        if (t + 1 < T) { GISSUE((t + 1) & 1, (t + 1) * 64, KDV); CP_COMMIT(); } \
        const int cur = t & 1; \
        uint32_t aH = smb + cur * 65536 + arow * 128; \
        uint32_t aL = aH + 16384; \
        uint32_t bB = smb + cur * 65536 + 32768 + (wn * 64 + brow) * 128; \
        _Pragma("unroll") \
        for (int ks = 0; ks < 4; ks++) { \
            uint32_t ac = ((uint32_t)((2 * ks + ah) ^ as)) << 4; \
            uint32_t aq[2][4], alr[2][4], bhh[4][4], bll[4][4]; \
            ldsm4(aq[0][0], aq[0][1], aq[0][2], aq[0][3], aH + ac); \
            ldsm4(aq[1][0], aq[1][1], aq[1][2], aq[1][3], aH + 16 * 128 + ac); \
            ldsm4(alr[0][0], alr[0][1], alr[0][2], alr[0][3], aL + ac); \
            ldsm4(alr[1][0], alr[1][1], alr[1][2], alr[1][3], aL + 16 * 128 + ac); \
            uint32_t bc = ((uint32_t)((2 * ks + bh2) ^ bs)) << 4; \
            _Pragma("unroll") \
            for (int ni = 0; ni < 4; ni++) { \
                ldsm4(bhh[ni][0], bhh[ni][1], bhh[ni][2], bhh[ni][3], bB + ni * 2048 + bc); \
                ldsm4(bll[ni][0], bll[ni][1], bll[ni][2], bll[ni][3], bB + 16384 + ni * 2048 + bc); \
            } \
            _Pragma("unroll") \
            for (int ni = 0; ni < 4; ni++) { \
                _Pragma("unroll") \
                for (int mi = 0; mi < 2; mi++) { \
                    mma_bf16(acc[mi][2*ni],   aq[mi],  bhh[ni][0], bhh[ni][1]); \
                    mma_bf16(acc[mi][2*ni],   aq[mi],  bll[ni][0], bll[ni][1]); \
                    mma_bf16(acc[mi][2*ni],   alr[mi], bhh[ni][0], bhh[ni][1]); \
                    mma_bf16(acc[mi][2*ni+1], aq[mi],  bhh[ni][2], bhh[ni][3]); \
                    mma_bf16(acc[mi][2*ni+1], aq[mi],  bll[ni][2], bll[ni][3]); \
                    mma_bf16(acc[mi][2*ni+1], alr[mi], bhh[ni][2], bhh[ni][3]); \
                } \
            } \
        } \
        __syncthreads(); \
    }

__global__ void __launch_bounds__(256, 1) gemm_qkv(
    const __nv_bfloat16* __restrict__ f1h, const __nv_bfloat16* __restrict__ f1l,
    const __nv_bfloat16* __restrict__ f2h, const __nv_bfloat16* __restrict__ f2l,
    const __nv_bfloat16* __restrict__ wqh, const __nv_bfloat16* __restrict__ wql,
    const __nv_bfloat16* __restrict__ wkh, const __nv_bfloat16* __restrict__ wkl,
    const __nv_bfloat16* __restrict__ wvh, const __nv_bfloat16* __restrict__ wvl,
    const float* __restrict__ bq, const float* __restrict__ bk, const float* __restrict__ bv,
    __nv_bfloat16* __restrict__ Qh, __nv_bfloat16* __restrict__ Ql,
    __nv_bfloat16* __restrict__ Kh, __nv_bfloat16* __restrict__ Kl,
    __nv_bfloat16* __restrict__ VTh, __nv_bfloat16* __restrict__ VTl)
{
    extern __shared__ char sm[];
    const uint32_t smb = smem_to_u32(sm);
    const int tid = threadIdx.x, lane = tid & 31, wid = tid >> 5;
    const int wm = wid & 3, wn = wid >> 2;
    const int n0 = blockIdx.x * 128, m0 = blockIdx.y * 128;
    const int z = blockIdx.z;

    const __nv_bfloat16* Ah = z == 0 ? f1h : f2h;
    const __nv_bfloat16* Al = z == 0 ? f1l : f2l;
    const __nv_bfloat16* Bh = z == 0 ? wqh : (z == 1 ? wkh : wvh);
    const __nv_bfloat16* Bl = z == 0 ? wql : (z == 1 ? wkl : wvl);
    const float* bias = z == 0 ? bq : (z == 1 ? bk : bv);
    __nv_bfloat16* Oh = z == 0 ? Qh : (z == 1 ? Kh : VTh);
    __nv_bfloat16* Ol = z == 0 ? Ql : (z == 1 ? Kl : VTl);

    const int arow = wm * 32 + (lane & 15);
    const int as = arow & 7, ah = lane >> 4;
    const int brow = ((lane >> 4) << 3) + (lane & 7);
    const int bs = lane & 7, bh2 = (lane >> 3) & 1;

    GEMM_BODY(D_)

    const int lq = lane & 3;
    #pragma unroll
    for (int mi = 0; mi < 2; mi++) {
        int r0 = m0 + wm * 32 + mi * 16 + (lane >> 2);
        int r1 = r0 + 8;
        #pragma unroll
        for (int nt = 0; nt < 8; nt++) {
            int col = n0 + wn * 64 + nt * 8 + 2 * lq;
            float b0 = bias[col], b1 = bias[col + 1];
            float v0 = acc[mi][nt][0] + b0, v1 = acc[mi][nt][1] + b1;
            float v2 = acc[mi][nt][2] + b0, v3 = acc[mi][nt][3] + b1;
            __nv_bfloat16 h0,l0,h1,l1,h2,l2,h3,l3;
            split_bf16(v0,h0,l0); split_bf16(v1,h1,l1);
            split_bf16(v2,h2,l2); split_bf16(v3,h3,l3);
            if (z < 2) {
                size_t o0 = (size_t)r0 * 256 + col, o1 = (size_t)r1 * 256 + col;
                *(uint32_t*)(Oh + o0) = pack2(h0, h1);
                *(uint32_t*)(Ol + o0) = pack2(l0, l1);
                *(uint32_t*)(Oh + o1) = pack2(h2, h3);
                *(uint32_t*)(Ol + o1) = pack2(l2, l3);
            } else {
                size_t o0 = (size_t)(r0 >> 11) * (F_ * S2_) + (size_t)col * S2_ + (r0 & 2047);
                size_t o1 = (size_t)(r1 >> 11) * (F_ * S2_) + (size_t)col * S2_ + (r1 & 2047);
                Oh[o0] = h0; Oh[o0 + S2_] = h1; Ol[o0] = l0; Ol[o0 + S2_] = l1;
                Oh[o1] = h2; Oh[o1 + S2_] = h3; Ol[o1] = l2; Ol[o1 + S2_] = l3;
            }
        }
    }
}

__global__ void __launch_bounds__(256, 1) gemm_fc(
    const __nv_bfloat16* __restrict__ Ah, const __nv_bfloat16* __restrict__ Al,
    const __nv_bfloat16* __restrict__ Bh, const __nv_bfloat16* __restrict__ Bl,
    const float* __restrict__ bias, float* __restrict__ Cf)
{
    extern __shared__ char sm[];
    const uint32_t smb = smem_to_u32(sm);
    const int tid = threadIdx.x, lane = tid & 31, wid = tid >> 5;
    const int wm = wid & 3, wn = wid >> 2;
    const int n0 = blockIdx.x * 128, m0 = blockIdx.y * 128;
    const int arow = wm * 32 + (lane & 15);
    const int as = arow & 7, ah = lane >> 4;
    const int brow = ((lane >> 4) << 3) + (lane & 7);
    const int bs = lane & 7, bh2 = (lane >> 3) & 1;

    GEMM_BODY(F_)

    const int lq = lane & 3;
    #pragma unroll
    for (int mi = 0; mi < 2; mi++) {
        int r0 = m0 + wm * 32 + mi * 16 + (lane >> 2);
        int r1 = r0 + 8;
        #pragma unroll
        for (int nt = 0; nt < 8; nt++) {
            int col = n0 + wn * 64 + nt * 8 + 2 * lq;
            float b0 = bias[col], b1 = bias[col + 1];
            *(float2*)(Cf + (size_t)r0 * 256 + col) = make_float2(acc[mi][nt][0] + b0, acc[mi][nt][1] + b1);
            *(float2*)(Cf + (size_t)r1 * 256 + col) = make_float2(acc[mi][nt][2] + b0, acc[mi][nt][3] + b1);
        }
    }
}

// HMMA flash attention: 512 threads (16 warps = 8 qg x 2 kh), BQA=128,
// BKA=32 double-buffered, Qh frags in regs, packed P, batched ldsm.
#define BQA 128
#define BKA 32
#define NKT (S2_ / BKA)
#define AQL 0
#define AKH(b) (65536 + (b) * 65536)
#define AKL(b) (81920 + (b) * 65536)
#define AV(b)  (98304 + (b) * 65536)
#define APS 196608
#define ALS 212992
#define ATTN_SMEM (212992 + 1024)

#define AISSUE(buf, kt) do { \
    _Pragma("unroll") \
    for (int p = 0; p < 2; p++) { \
        int id = p * 512 + tid; int r = id >> 5, c = id & 31; \
        uint32_t d = r * 512 + (((uint32_t)(c ^ (r & 7))) << 4); \
        CP_ASYNC16(smb + AKH(buf) + d, Khb + (size_t)((kt) + r) * F_ + c * 8); \
        CP_ASYNC16(smb + AKL(buf) + d, Klb + (size_t)((kt) + r) * F_ + c * 8); \
    } \
    _Pragma("unroll") \
    for (int p = 0; p < 4; p++) { \
        int id = p * 512 + tid; int r = id >> 3, c = id & 7; \
        const __nv_bfloat16* src = (c < 4) ? (Vhb + (size_t)r * S2_ + (kt) + c * 8) \
                                           : (Vlb + (size_t)r * S2_ + (kt) + (c - 4) * 8); \
        CP_ASYNC16(smb + AV(buf) + r * 128 + (((uint32_t)(c ^ (r & 7))) << 4), src); \
    } } while (0)

__global__ void __launch_bounds__(512, 1) attn_kernel(
    const __nv_bfloat16* __restrict__ Qh, const __nv_bfloat16* __restrict__ Ql,
    const __nv_bfloat16* __restrict__ Kh, const __nv_bfloat16* __restrict__ Kl,
    const __nv_bfloat16* __restrict__ VTh, const __nv_bfloat16* __restrict__ VTl,
    __nv_bfloat16* __restrict__ AOh, __nv_bfloat16* __restrict__ AOl)
{
    extern __shared__ char sm[];
    const uint32_t smb = smem_to_u32(sm);
    const int tid = threadIdx.x, wid = tid >> 5, lane = tid & 31;
    const int b = blockIdx.y, q0 = blockIdx.x * BQA;
    const int qg = wid >> 1, kh = wid & 1;

    const __nv_bfloat16* Khb = Kh  + (size_t)b * S2_ * F_;
    const __nv_bfloat16* Klb = Kl  + (size_t)b * S2_ * F_;
    const __nv_bfloat16* Vhb = VTh + (size_t)b * F_ * S2_;
    const __nv_bfloat16* Vlb = VTl + (size_t)b * F_ * S2_;
    const __nv_bfloat16* Qlb = Ql  + ((size_t)(b * S1_ + q0)) * F_;
    const __nv_bfloat16* Qhb = Qh  + ((size_t)(b * S1_ + q0)) * F_;

    AISSUE(0, 0);
    #pragma unroll
    for (int p = 0; p < 8; p++) {
        int id = p * 512 + tid;
        int r = id >> 5, c = id & 31;
        uint32_t d = r * 512 + (((uint32_t)(c ^ (r & 7))) << 4);
        CP_ASYNC16(smb + AQL + d, Qlb + (size_t)r * F_ + c * 8);
    }
    CP_COMMIT();

    const int fr0 = qg * 16 + (lane >> 2);
    const int fcc = (lane & 3) * 2;
    uint32_t qf[16][4];
    #pragma unroll
    for (int ks = 0; ks < 16; ks++) {
        qf[ks][0] = *(const uint32_t*)(Qhb + (size_t)fr0 * F_ + 16 * ks + fcc);
        qf[ks][1] = *(const uint32_t*)(Qhb + (size_t)(fr0 + 8) * F_ + 16 * ks + fcc);
        qf[ks][2] = *(const uint32_t*)(Qhb + (size_t)fr0 * F_ + 16 * ks + 8 + fcc);
        qf[ks][3] = *(const uint32_t*)(Qhb + (size_t)(fr0 + 8) * F_ + 16 * ks + 8 + fcc);
    }

    const int arow = qg * 16 + (lane & 15);
    const int as = arow & 7, ah = lane >> 4;
    const uint32_t qlB = smb + AQL + arow * 512;
    const uint32_t pB  = smb + APS + arow * 128;
    const int brow = ((lane >> 4) << 3) + (lane & 7);
    const int bs = lane & 7, bh2 = (lane >> 3) & 1;
    const int crow = qg * 16 + (lane >> 2);
    const int lq = lane & 3;

    float accO[16][4];
    #pragma unroll
    for (int i = 0; i < 16; i++)
        #pragma unroll
        for (int j = 0; j < 4; j++) accO[i][j] = 0.f;
    float lsum0 = 0.f, lsum1 = 0.f;
    const float scale = 0.0625f;

    for (int it = 0; it < NKT; it++) {
        const int cur = it & 1;
        CP_WAIT0();
        __syncthreads();
        if (it + 1 < NKT) { AISSUE(cur ^ 1, (it + 1) * BKA); CP_COMMIT(); }

        // S = Qh@Kh + Qh@Kl + Ql@Kh, k-steps processed in pairs (6 ldsm -> 12 mma)
        float sa[2][4];
        #pragma unroll
        for (int j = 0; j < 4; j++) { sa[0][j] = 0.f; sa[1][j] = 0.f; }
        const uint32_t kbH = smb + AKH(cur) + (kh * 16 + brow) * 512;
        const uint32_t kbL = smb + AKL(cur) + (kh * 16 + brow) * 512;
        #pragma unroll
        for (int kp = 0; kp < 8; kp++) {
            uint32_t al4[2][4], bh4[2][4], bl4[2][4];
            #pragma unroll
            for (int u = 0; u < 2; u++) {
                int ks = 2 * kp + u;
                uint32_t qc = ((uint32_t)((2 * ks + ah) ^ as)) << 4;
                ldsm4(al4[u][0], al4[u][1], al4[u][2], al4[u][3], qlB + qc);
                uint32_t kc = ((uint32_t)((2 * ks + bh2) ^ bs)) << 4;
                ldsm4(bh4[u][0], bh4[u][1], bh4[u][2], bh4[u][3], kbH + kc);
                ldsm4(bl4[u][0], bl4[u][1], bl4[u][2], bl4[u][3], kbL + kc);
            }
            #pragma unroll
            for (int u = 0; u < 2; u++) {
                int ks = 2 * kp + u;
                mma_bf16(sa[0], qf[ks], bh4[u][0], bh4[u][1]);
                mma_bf16(sa[0], qf[ks], bl4[u][0], bl4[u][1]);
                mma_bf16(sa[0], al4[u], bh4[u][0], bh4[u][1]);
                mma_bf16(sa[1], qf[ks], bh4[u][2], bh4[u][3]);
                mma_bf16(sa[1], qf[ks], bl4[u][2], bl4[u][3]);
                mma_bf16(sa[1], al4[u], bh4[u][2], bh4[u][3]);
            }
        }

        // softmax (no max-sub), split, store packed P (hi ch0-3 / lo ch4-7)
        {
            const int rA = crow, rB = crow + 8;
            #pragma unroll
            for (int nt = 0; nt < 2; nt++) {
                float p0 = __expf(sa[nt][0] * scale);
                float p1 = __expf(sa[nt][1] * scale);
                float p2 = __expf(sa[nt][2] * scale);
                float p3 = __expf(sa[nt][3] * scale);
                lsum0 += p0 + p1;
                lsum1 += p2 + p3;
                int hc = kh * 2 + nt;
                uint32_t hA = (uint32_t)(rA * 128 + ((hc ^ (rA & 7)) << 4) + lq * 4);
                uint32_t hB = (uint32_t)(rB * 128 + ((hc ^ (rB & 7)) << 4) + lq * 4);
                uint32_t lA = (uint32_t)(rA * 128 + (((hc + 4) ^ (rA & 7)) << 4) + lq * 4);
                uint32_t lB = (uint32_t)(rB * 128 + (((hc + 4) ^ (rB & 7)) << 4) + lq * 4);
                __nv_bfloat16 h0,l0,h1,l1,h2,l2,h3,l3;
                split_bf16(p0,h0,l0); split_bf16(p1,h1,l1);
                split_bf16(p2,h2,l2); split_bf16(p3,h3,l3);
                *(uint32_t*)(sm + APS + hA) = pack2(h0, h1);
                *(uint32_t*)(sm + APS + hB) = pack2(h2, h3);
                *(uint32_t*)(sm + APS + lA) = pack2(l0, l1);
                *(uint32_t*)(sm + APS + lB) = pack2(l2, l3);
            }
        }
        __syncthreads();

        // O += Ph@Vh + Ph@Vl + Pl@Vh, per np: 4 ldsm -> 12 mma
        {
            uint32_t pf[2][4], plf[2][4];
            #pragma unroll
            for (int ks = 0; ks < 2; ks++) {
                uint32_t hc = (uint32_t)(2 * ks + ah);
                ldsm4(pf[ks][0], pf[ks][1], pf[ks][2], pf[ks][3], pB + ((hc ^ (uint32_t)as) << 4));
                ldsm4(plf[ks][0], plf[ks][1], plf[ks][2], plf[ks][3], pB + (((hc + 4) ^ (uint32_t)as) << 4));
            }
            const uint32_t vb = smb + AV(cur) + (kh * 128 + brow) * 128;
            #pragma unroll
            for (int np = 0; np < 8; np++) {
                uint32_t vh4[2][4], vl4[2][4];
                uint32_t base = vb + np * 16 * 128;
                #pragma unroll
                for (int ks = 0; ks < 2; ks++) {
                    uint32_t ch = (uint32_t)(2 * ks + bh2);
                    ldsm4(vh4[ks][0], vh4[ks][1], vh4[ks][2], vh4[ks][3], base + ((ch ^ (uint32_t)bs) << 4));
                    ldsm4(vl4[ks][0], vl4[ks][1], vl4[ks][2], vl4[ks][3], base + (((ch + 4) ^ (uint32_t)bs) << 4));
                }
                const int n0 = np * 2, n1 = np * 2 + 1;
                #pragma unroll
                for (int ks = 0; ks < 2; ks++) {
                    mma_bf16(accO[n0], pf[ks],  vh4[ks][0], vh4[ks][1]);
                    mma_bf16(accO[n0], pf[ks],  vl4[ks][0], vl4[ks][1]);
                    mma_bf16(accO[n0], plf[ks], vh4[ks][0], vh4[ks][1]);
                    mma_bf16(accO[n1], pf[ks],  vh4[ks][2], vh4[ks][3]);
                    mma_bf16(accO[n1], pf[ks],  vl4[ks][2], vl4[ks][3]);
                    mma_bf16(accO[n1], plf[ks], vh4[ks][2], vh4[ks][3]);
                }
            }
        }
    }

    float* lsm = (float*)(sm + ALS);
    lsum0 += __shfl_xor_sync(0xffffffffu, lsum0, 1);
    lsum0 += __shfl_xor_sync(0xffffffffu, lsum0, 2);
    lsum1 += __shfl_xor_sync(0xffffffffu, lsum1, 1);
    lsum1 += __shfl_xor_sync(0xffffffffu, lsum1, 2);
    __syncthreads();
    if (lq == 0) {
        lsm[kh * 128 + crow]     = lsum0;
        lsm[kh * 128 + crow + 8] = lsum1;
    }
    __syncthreads();

    const float inv0 = 1.f / (lsm[crow]     + lsm[128 + crow]);
    const float inv1 = 1.f / (lsm[crow + 8] + lsm[128 + crow + 8]);
    const size_t base0 = ((size_t)(b * S1_ + q0 + crow)) * F_;
    const size_t base1 = ((size_t)(b * S1_ + q0 + crow + 8)) * F_;
    #pragma unroll
    for (int nt = 0; nt < 16; nt++) {
        int col = kh * 128 + nt * 8 + 2 * lq;
        __nv_bfloat16 h0,l0,h1,l1,h2,l2,h3,l3;
        split_bf16(accO[nt][0] * inv0, h0, l0);
        split_bf16(accO[nt][1] * inv0, h1, l1);
        split_bf16(accO[nt][2] * inv1, h2, l2);
        split_bf16(accO[nt][3] * inv1, h3, l3);
        *(uint32_t*)(AOh + base0 + col) = pack2(h0, h1);
        *(uint32_t*)(AOl + base0 + col) = pack2(l0, l1);
        *(uint32_t*)(AOh + base1 + col) = pack2(h2, h3);
        *(uint32_t*)(AOl + base1 + col) = pack2(l2, l3);
    }
}

extern "C" void kernel_launch(void* const* d_in, const int* in_sizes, int n_in,
                              void* d_out, int out_size)
{
    const float* feat1 = (const float*)d_in[0];
    const float* feat2 = (const float*)d_in[1];
    const float* Wq    = (const float*)d_in[2];
    const float* bq    = (const float*)d_in[3];
    const float* Wk    = (const float*)d_in[4];
    const float* bk    = (const float*)d_in[5];
    const float* Wv    = (const float*)d_in[6];
    const float* bv    = (const float*)d_in[7];
    const float* Wfc   = (const float*)d_in[8];
    const float* bfc   = (const float*)d_in[9];
    float* out = (float*)d_out;

    __nv_bfloat16 *f1h, *f1l, *f2h, *f2l, *Qh, *Ql, *Kh, *Kl, *VTh, *VTl, *AOh, *AOl;
    __nv_bfloat16 (*wq)[D_ * F_]; __nv_bfloat16 (*wk)[D_ * F_];
    __nv_bfloat16 (*wv)[D_ * F_]; __nv_bfloat16 (*wf)[F_ * F_];
    cudaGetSymbolAddress((void**)&f1h, g_f1h);
    cudaGetSymbolAddress((void**)&f1l, g_f1l);
    cudaGetSymbolAddress((void**)&f2h, g_f2h);
    cudaGetSymbolAddress((void**)&f2l, g_f2l);
    cudaGetSymbolAddress((void**)&wq,  g_wq);
    cudaGetSymbolAddress((void**)&wk,  g_wk);
    cudaGetSymbolAddress((void**)&wv,  g_wv);
    cudaGetSymbolAddress((void**)&wf,  g_wf);
    cudaGetSymbolAddress((void**)&Qh,  g_Qh);
    cudaGetSymbolAddress((void**)&Ql,  g_Ql);
    cudaGetSymbolAddress((void**)&Kh,  g_Kh);
    cudaGetSymbolAddress((void**)&Kl,  g_Kl);
    cudaGetSymbolAddress((void**)&VTh, g_VTh);
    cudaGetSymbolAddress((void**)&VTl, g_VTl);
    cudaGetSymbolAddress((void**)&AOh, g_AOh);
    cudaGetSymbolAddress((void**)&AOl, g_AOl);

    split_f32_kernel<<<NFEAT / 4 / 256, 256>>>(feat1, f1h, f1l, NFEAT / 4);
    split_f32_kernel<<<NFEAT / 4 / 256, 256>>>(feat2, f2h, f2l, NFEAT / 4);
    split_weights_kernel<<<(3 * D_ * F_ + F_ * F_ + 255) / 256, 256>>>(
        Wq, Wk, Wv, Wfc, wq[0], wq[1], wk[0], wk[1], wv[0], wv[1], wf[0], wf[1]);

    cudaFuncSetAttribute(gemm_qkv, cudaFuncAttributeMaxDynamicSharedMemorySize, GEMM_SMEM);
    cudaFuncSetAttribute(gemm_fc,  cudaFuncAttributeMaxDynamicSharedMemorySize, GEMM_SMEM);
    cudaFuncSetAttribute(attn_kernel, cudaFuncAttributeMaxDynamicSharedMemorySize, ATTN_SMEM);

    dim3 gq(2, B_ * S1_ / 128, 3);
    gemm_qkv<<<gq, 256, GEMM_SMEM>>>(f1h, f1l, f2h, f2l,
                                     wq[0], wq[1], wk[0], wk[1], wv[0], wv[1],
                                     bq, bk, bv, Qh, Ql, Kh, Kl, VTh, VTl);

    dim3 ag(S1_ / BQA, B_);
    attn_kernel<<<ag, 512, ATTN_SMEM>>>(Qh, Ql, Kh, Kl, VTh, VTl, AOh, AOl);

    dim3 gg(2, B_ * S1_ / 128);
    gemm_fc<<<gg, 256, GEMM_SMEM>>>(AOh, AOl, wf[0], wf[1], bfc, out);
}

// round 11
// speedup vs baseline: 1.8935x; 1.2566x over previous
#include <cuda_runtime.h>
#include <cuda_bf16.h>
#include <cstdint>

#define B_  8
#define S1_ 2048
#define S2_ 2048
#define D_  512
#define F_  256
#define NQKV (B_ * S1_ * F_)
#define NFEAT (B_ * S1_ * D_)
#define NP   (B_ * S1_ * S2_)

__device__ __align__(16) __nv_bfloat16 g_f1h[NFEAT];
__device__ __align__(16) __nv_bfloat16 g_f1l[NFEAT];
__device__ __align__(16) __nv_bfloat16 g_f2h[NFEAT];
__device__ __align__(16) __nv_bfloat16 g_f2l[NFEAT];
__device__ __align__(16) __nv_bfloat16 g_wq[2][D_ * F_];
__device__ __align__(16) __nv_bfloat16 g_wk[2][D_ * F_];
__device__ __align__(16) __nv_bfloat16 g_wv[2][D_ * F_];
__device__ __align__(16) __nv_bfloat16 g_wf[2][F_ * F_];
__device__ __align__(16) __nv_bfloat16 g_Qh [NQKV];
__device__ __align__(16) __nv_bfloat16 g_Ql [NQKV];
__device__ __align__(16) __nv_bfloat16 g_Kh [NQKV];
__device__ __align__(16) __nv_bfloat16 g_Kl [NQKV];
__device__ __align__(16) __nv_bfloat16 g_VTh[NQKV];   // [b, f, t]
__device__ __align__(16) __nv_bfloat16 g_VTl[NQKV];
__device__ __align__(16) __nv_bfloat16 g_Ph [NP];     // [b*2048+q][2048]
__device__ __align__(16) __nv_bfloat16 g_Pl [NP];
__device__ __align__(16) float         g_lp [B_ * S1_ * 16];
__device__ __align__(16) float         g_l  [B_ * S1_];
__device__ __align__(16) __nv_bfloat16 g_AOh[NQKV];
__device__ __align__(16) __nv_bfloat16 g_AOl[NQKV];

__device__ __forceinline__ uint32_t smem_to_u32(const void* p) {
    uint32_t a;
    asm("{ .reg .u64 t; cvta.to.shared.u64 t, %1; cvt.u32.u64 %0, t; }" : "=r"(a) : "l"(p));
    return a;
}
__device__ __forceinline__ void ldsm4(uint32_t* r, uint32_t a) {
    asm volatile("ldmatrix.sync.aligned.m8n8.x4.shared.b16 {%0,%1,%2,%3}, [%4];"
        : "=r"(r[0]), "=r"(r[1]), "=r"(r[2]), "=r"(r[3]) : "r"(a));
}
__device__ __forceinline__ void mma_bf16(float (&d)[4], const uint32_t* a, uint32_t b0, uint32_t b1) {
    asm volatile("mma.sync.aligned.m16n8k16.row.col.f32.bf16.bf16.f32 "
        "{%0,%1,%2,%3}, {%4,%5,%6,%7}, {%8,%9}, {%0,%1,%2,%3};"
        : "+f"(d[0]), "+f"(d[1]), "+f"(d[2]), "+f"(d[3])
        : "r"(a[0]), "r"(a[1]), "r"(a[2]), "r"(a[3]), "r"(b0), "r"(b1));
}
__device__ __forceinline__ void split_bf16(float x, __nv_bfloat16& h, __nv_bfloat16& l) {
    h = __float2bfloat16(x);
    l = __float2bfloat16(x - __bfloat162float(h));
}
__device__ __forceinline__ uint32_t pack2(__nv_bfloat16 a, __nv_bfloat16 b) {
    return (uint32_t)__bfloat16_as_ushort(a) | ((uint32_t)__bfloat16_as_ushort(b) << 16);
}
#define CP_ASYNC16(dst, src) asm volatile("cp.async.cg.shared.global [%0], [%1], 16;" :: "r"(dst), "l"(src))
#define CP_COMMIT() asm volatile("cp.async.commit_group;" ::: "memory")
#define CP_WAIT0()  asm volatile("cp.async.wait_group 0;" ::: "memory")

__global__ void __launch_bounds__(256) split_f32_kernel(
    const float* __restrict__ in, __nv_bfloat16* __restrict__ h,
    __nv_bfloat16* __restrict__ l, int n4)
{
    int i = blockIdx.x * 256 + threadIdx.x;
    if (i >= n4) return;
    float4 v = ((const float4*)in)[i];
    __nv_bfloat16 h0,l0,h1,l1,h2,l2,h3,l3;
    split_bf16(v.x,h0,l0); split_bf16(v.y,h1,l1);
    split_bf16(v.z,h2,l2); split_bf16(v.w,h3,l3);
    ((uint2*)h)[i] = make_uint2(pack2(h0,h1), pack2(h2,h3));
    ((uint2*)l)[i] = make_uint2(pack2(l0,l1), pack2(l2,l3));
}

__global__ void __launch_bounds__(256) split_weights_kernel(
    const float* __restrict__ Wq, const float* __restrict__ Wk,
    const float* __restrict__ Wv, const float* __restrict__ Wfc,
    __nv_bfloat16* __restrict__ wq0, __nv_bfloat16* __restrict__ wq1,
    __nv_bfloat16* __restrict__ wk0, __nv_bfloat16* __restrict__ wk1,
    __nv_bfloat16* __restrict__ wv0, __nv_bfloat16* __restrict__ wv1,
    __nv_bfloat16* __restrict__ wf0, __nv_bfloat16* __restrict__ wf1)
{
    int i = blockIdx.x * 256 + threadIdx.x;
    const int NW = D_ * F_;
    __nv_bfloat16 h, l;
    if (i < 3 * NW) {
        int which = i / NW, j = i - which * NW;
        int n = j / D_, k = j - n * D_;
        const float* W = which == 0 ? Wq : (which == 1 ? Wk : Wv);
        split_bf16(W[(size_t)k * F_ + n], h, l);
        __nv_bfloat16* Th = which == 0 ? wq0 : (which == 1 ? wk0 : wv0);
        __nv_bfloat16* Tl = which == 0 ? wq1 : (which == 1 ? wk1 : wv1);
        Th[j] = h; Tl[j] = l;
    } else {
        int j = i - 3 * NW;
        if (j >= F_ * F_) return;
        int n = j / F_, k = j - n * F_;
        split_bf16(Wfc[(size_t)k * F_ + n], h, l);
        wf0[j] = h; wf1[j] = l;
    }
}

// ---------------------------------------------------------------------------
// Shared HMMA GEMM body: CTA 128x128, 256 thr, 8 warps (2m x 4n), warp 64x32.
// k-block 32, 2-stage cp.async, packed hi|lo 128B smem rows. 64KB smem.
// Needs in scope: Ah,Al,Bh,Bl (bf16*), ma, nb (row offsets).
// ---------------------------------------------------------------------------
#define GEMM_SMEM 65536

#define GEMM_PROLOG \
    extern __shared__ char sm[]; \
    const uint32_t smb = smem_to_u32(sm); \
    const int tid = threadIdx.x, lane = tid & 31, wid = tid >> 5; \
    const int wm = wid & 1, wn = wid >> 1; \
    const int arow = wm * 64 + (lane & 15); \
    const int as = arow & 7, ah = lane >> 4; \
    const int brow = wn * 32 + ((lane >> 4) << 3) + (lane & 7); \
    const int bs = lane & 7, bh2 = (lane >> 3) & 1; \
    const int lq = lane & 3;

#define GISSUE(buf, k0, KDV) do { \
    uint32_t gb = smb + (buf) * 32768; \
    _Pragma("unroll") \
    for (int p = 0; p < 4; p++) { \
        int id = p * 256 + tid; int r = id >> 3, c = id & 7; \
        uint32_t d = r * 128 + (((uint32_t)(c ^ (r & 7))) << 4); \
        const __nv_bfloat16* sa = (c < 4) ? Ah + (size_t)(ma + r) * (KDV) + (k0) + c * 8 \
                                          : Al + (size_t)(ma + r) * (KDV) + (k0) + (c - 4) * 8; \
        CP_ASYNC16(gb + d, sa); \
        const __nv_bfloat16* sb = (c < 4) ? Bh + (size_t)(nb + r) * (KDV) + (k0) + c * 8 \
                                          : Bl + (size_t)(nb + r) * (KDV) + (k0) + (c - 4) * 8; \
        CP_ASYNC16(gb + 16384 + d, sb); \
    } } while (0)

#define GEMM_MAIN(KDV) \
    float acc[4][4][4]; \
    _Pragma("unroll") \
    for (int i = 0; i < 4; i++) \
        _Pragma("unroll") \
        for (int j = 0; j < 4; j++) \
            _Pragma("unroll") \
            for (int k = 0; k < 4; k++) acc[i][j][k] = 0.f; \
    { \
        const int T = (KDV) / 32; \
        GISSUE(0, 0, KDV); CP_COMMIT(); \
        for (int t = 0; t < T; t++) { \
            CP_WAIT0(); \
            __syncthreads(); \
            if (t + 1 < T) { GISSUE((t + 1) & 1, (t + 1) * 32, KDV); CP_COMMIT(); } \
            const int cur = t & 1; \
            uint32_t aP = smb + cur * 32768 + arow * 128; \
            uint32_t bP = smb + cur * 32768 + 16384 + brow * 128; \
            _Pragma("unroll") \
            for (int ks = 0; ks < 2; ks++) { \
                uint32_t hcA = (uint32_t)(2 * ks + ah); \
                uint32_t aq[4][4], alr[4][4]; \
                _Pragma("unroll") \
                for (int mi = 0; mi < 4; mi++) { \
                    ldsm4(aq[mi],  aP + mi * 2048 + ((hcA ^ (uint32_t)as) << 4)); \
                    ldsm4(alr[mi], aP + mi * 2048 + (((hcA + 4) ^ (uint32_t)as) << 4)); \
                } \
                uint32_t hcB = (uint32_t)(2 * ks + bh2); \
                _Pragma("unroll") \
                for (int ni = 0; ni < 2; ni++) { \
                    uint32_t bhh[4], bll[4]; \
                    ldsm4(bhh, bP + ni * 2048 + ((hcB ^ (uint32_t)bs) << 4)); \
                    ldsm4(bll, bP + ni * 2048 + (((hcB + 4) ^ (uint32_t)bs) << 4)); \
                    _Pragma("unroll") \
                    for (int mi = 0; mi < 4; mi++) { \
                        mma_bf16(acc[mi][2*ni],   aq[mi],  bhh[0], bhh[1]); \
                        mma_bf16(acc[mi][2*ni],   aq[mi],  bll[0], bll[1]); \
                        mma_bf16(acc[mi][2*ni],   alr[mi], bhh[0], bhh[1]); \
                        mma_bf16(acc[mi][2*ni+1], aq[mi],  bhh[2], bhh[3]); \
                        mma_bf16(acc[mi][2*ni+1], aq[mi],  bll[2], bll[3]); \
                        mma_bf16(acc[mi][2*ni+1], alr[mi], bhh[2], bhh[3]); \
                    } \
                } \
            } \
            __syncthreads(); \
        } \
    }

// ---------------------------------------------------------------------------
// Fused Q/K/V projection GEMM: z selects product. KD=512.
// ---------------------------------------------------------------------------
__global__ void __launch_bounds__(256, 2) gemm_qkv(
    const __nv_bfloat16* __restrict__ f1h, const __nv_bfloat16* __restrict__ f1l,
    const __nv_bfloat16* __restrict__ f2h, const __nv_bfloat16* __restrict__ f2l,
    const __nv_bfloat16* __restrict__ wqh, const __nv_bfloat16* __restrict__ wql,
    const __nv_bfloat16* __restrict__ wkh, const __nv_bfloat16* __restrict__ wkl,
    const __nv_bfloat16* __restrict__ wvh, const __nv_bfloat16* __restrict__ wvl,
    const float* __restrict__ bq, const float* __restrict__ bk, const float* __restrict__ bv,
    __nv_bfloat16* __restrict__ Qh, __nv_bfloat16* __restrict__ Ql,
    __nv_bfloat16* __restrict__ Kh, __nv_bfloat16* __restrict__ Kl,
    __nv_bfloat16* __restrict__ VTh, __nv_bfloat16* __restrict__ VTl)
{
    GEMM_PROLOG
    const int n0 = blockIdx.x * 128, m0 = blockIdx.y * 128;
    const int z = blockIdx.z;
    const int ma = m0, nb = n0;
    const __nv_bfloat16* Ah = z == 0 ? f1h : f2h;
    const __nv_bfloat16* Al = z == 0 ? f1l : f2l;
    const __nv_bfloat16* Bh = z == 0 ? wqh : (z == 1 ? wkh : wvh);
    const __nv_bfloat16* Bl = z == 0 ? wql : (z == 1 ? wkl : wvl);
    const float* bias = z == 0 ? bq : (z == 1 ? bk : bv);
    __nv_bfloat16* Oh = z == 0 ? Qh : (z == 1 ? Kh : VTh);
    __nv_bfloat16* Ol = z == 0 ? Ql : (z == 1 ? Kl : VTl);

    GEMM_MAIN(D_)

    #pragma unroll
    for (int mi = 0; mi < 4; mi++) {
        int r0 = m0 + wm * 64 + mi * 16 + (lane >> 2);
        int r1 = r0 + 8;
        #pragma unroll
        for (int nt = 0; nt < 4; nt++) {
            int col = n0 + wn * 32 + nt * 8 + 2 * lq;
            float b0 = bias[col], b1 = bias[col + 1];
            float v0 = acc[mi][nt][0] + b0, v1 = acc[mi][nt][1] + b1;
            float v2 = acc[mi][nt][2] + b0, v3 = acc[mi][nt][3] + b1;
            __nv_bfloat16 h0,l0,h1,l1,h2,l2,h3,l3;
            split_bf16(v0,h0,l0); split_bf16(v1,h1,l1);
            split_bf16(v2,h2,l2); split_bf16(v3,h3,l3);
            if (z < 2) {
                size_t o0 = (size_t)r0 * 256 + col, o1 = (size_t)r1 * 256 + col;
                *(uint32_t*)(Oh + o0) = pack2(h0, h1);
                *(uint32_t*)(Ol + o0) = pack2(l0, l1);
                *(uint32_t*)(Oh + o1) = pack2(h2, h3);
                *(uint32_t*)(Ol + o1) = pack2(l2, l3);
            } else {
                size_t o0 = (size_t)(r0 >> 11) * (F_ * S2_) + (size_t)col * S2_ + (r0 & 2047);
                size_t o1 = (size_t)(r1 >> 11) * (F_ * S2_) + (size_t)col * S2_ + (r1 & 2047);
                Oh[o0] = h0; Oh[o0 + S2_] = h1; Ol[o0] = l0; Ol[o0 + S2_] = l1;
                Oh[o1] = h2; Oh[o1 + S2_] = h3; Ol[o1] = l2; Ol[o1 + S2_] = l3;
            }
        }
    }
}

// ---------------------------------------------------------------------------
// S-kernel: P = exp(scale * Q@K^T) split-bf16 + per-128-block row sums. KD=256.
// grid (kblk 16, qblk 16, batch 8)
// ---------------------------------------------------------------------------
__global__ void __launch_bounds__(256, 2) gemm_S(
    const __nv_bfloat16* __restrict__ Qh, const __nv_bfloat16* __restrict__ Ql,
    const __nv_bfloat16* __restrict__ Kh, const __nv_bfloat16* __restrict__ Kl,
    __nv_bfloat16* __restrict__ Ph, __nv_bfloat16* __restrict__ Pl,
    float* __restrict__ lp)
{
    GEMM_PROLOG
    const int kblk = blockIdx.x, qblk = blockIdx.y, b = blockIdx.z;
    const int ma = qblk * 128, nb = kblk * 128;
    const __nv_bfloat16* Ah = Qh + (size_t)b * S1_ * F_;
    const __nv_bfloat16* Al = Ql + (size_t)b * S1_ * F_;
    const __nv_bfloat16* Bh = Kh + (size_t)b * S2_ * F_;
    const __nv_bfloat16* Bl = Kl + (size_t)b * S2_ * F_;

    GEMM_MAIN(F_)

    const float scale = 0.0625f;
    const int bq0 = b * S1_ + qblk * 128;
    const int kb0 = kblk * 128;
    float rsum[4][2];
    #pragma unroll
    for (int mi = 0; mi < 4; mi++) { rsum[mi][0] = 0.f; rsum[mi][1] = 0.f; }

    #pragma unroll
    for (int mi = 0; mi < 4; mi++) {
        int rl0 = wm * 64 + mi * 16 + (lane >> 2);
        size_t pb0 = (size_t)(bq0 + rl0) * S2_ + kb0;
        size_t pb1 = (size_t)(bq0 + rl0 + 8) * S2_ + kb0;
        #pragma unroll
        for (int nt = 0; nt < 4; nt++) {
            int col = wn * 32 + nt * 8 + 2 * lq;
            float p0 = __expf(acc[mi][nt][0] * scale);
            float p1 = __expf(acc[mi][nt][1] * scale);
            float p2 = __expf(acc[mi][nt][2] * scale);
            float p3 = __expf(acc[mi][nt][3] * scale);
            rsum[mi][0] += p0 + p1;
            rsum[mi][1] += p2 + p3;
            __nv_bfloat16 h0,l0,h1,l1,h2,l2,h3,l3;
            split_bf16(p0,h0,l0); split_bf16(p1,h1,l1);
            split_bf16(p2,h2,l2); split_bf16(p3,h3,l3);
            *(uint32_t*)(Ph + pb0 + col) = pack2(h0, h1);
            *(uint32_t*)(Pl + pb0 + col) = pack2(l0, l1);
            *(uint32_t*)(Ph + pb1 + col) = pack2(h2, h3);
            *(uint32_t*)(Pl + pb1 + col) = pack2(l2, l3);
        }
    }
    // reduce row sums: shfl within lq quad, then across 4 wn via smem
    #pragma unroll
    for (int mi = 0; mi < 4; mi++) {
        #pragma unroll
        for (int u = 0; u < 2; u++) {
            rsum[mi][u] += __shfl_xor_sync(0xffffffffu, rsum[mi][u], 1);
            rsum[mi][u] += __shfl_xor_sync(0xffffffffu, rsum[mi][u], 2);
        }
    }
    float* red = (float*)sm;
    __syncthreads();
    if (lq == 0) {
        #pragma unroll
        for (int mi = 0; mi < 4; mi++) {
            int rl = wm * 64 + mi * 16 + (lane >> 2);
            red[wn * 128 + rl]     = rsum[mi][0];
            red[wn * 128 + rl + 8] = rsum[mi][1];
        }
    }
    __syncthreads();
    if (tid < 128)
        lp[(size_t)(bq0 + tid) * 16 + kblk] =
            (red[tid] + red[128 + tid]) + (red[256 + tid] + red[384 + tid]);
}

__global__ void __launch_bounds__(256) lreduce_kernel(const float* __restrict__ lp,
                                                      float* __restrict__ l)
{
    int i = blockIdx.x * 256 + threadIdx.x;
    if (i >= B_ * S1_) return;
    float s = 0.f;
    #pragma unroll
    for (int j = 0; j < 16; j++) s += lp[(size_t)i * 16 + j];
    l[i] = s;
}

// ---------------------------------------------------------------------------
// PV-kernel: O = (P@VT^T) / l, split-bf16 out. KD=2048.
// grid (fblk 2, qblk 16, batch 8)
// ---------------------------------------------------------------------------
__global__ void __launch_bounds__(256, 2) gemm_pv(
    const __nv_bfloat16* __restrict__ Ph, const __nv_bfloat16* __restrict__ Pl,
    const __nv_bfloat16* __restrict__ VTh, const __nv_bfloat16* __restrict__ VTl,
    const float* __restrict__ l,
    __nv_bfloat16* __restrict__ AOh, __nv_bfloat16* __restrict__ AOl)
{
    GEMM_PROLOG
    const int fblk = blockIdx.x, qblk = blockIdx.y, b = blockIdx.z;
    const int ma = qblk * 128, nb = fblk * 128;
    const __nv_bfloat16* Ah = Ph + (size_t)b * S1_ * S2_;
    const __nv_bfloat16* Al = Pl + (size_t)b * S1_ * S2_;
    const __nv_bfloat16* Bh = VTh + (size_t)b * F_ * S2_;
    const __nv_bfloat16* Bl = VTl + (size_t)b * F_ * S2_;

    GEMM_MAIN(S2_)

    const int bq0 = b * S1_ + qblk * 128;
    #pragma unroll
    for (int mi = 0; mi < 4; mi++) {
        int rl0 = wm * 64 + mi * 16 + (lane >> 2);
        float inv0 = 1.f / l[bq0 + rl0];
        float inv1 = 1.f / l[bq0 + rl0 + 8];
        size_t o0 = (size_t)(bq0 + rl0) * 256;
        size_t o1 = (size_t)(bq0 + rl0 + 8) * 256;
        #pragma unroll
        for (int nt = 0; nt < 4; nt++) {
            int col = fblk * 128 + wn * 32 + nt * 8 + 2 * lq;
            __nv_bfloat16 h0,l0,h1,l1,h2,l2,h3,l3;
            split_bf16(acc[mi][nt][0] * inv0, h0, l0);
            split_bf16(acc[mi][nt][1] * inv0, h1, l1);
            split_bf16(acc[mi][nt][2] * inv1, h2, l2);
            split_bf16(acc[mi][nt][3] * inv1, h3, l3);
            *(uint32_t*)(AOh + o0 + col) = pack2(h0, h1);
            *(uint32_t*)(AOl + o0 + col) = pack2(l0, l1);
            *(uint32_t*)(AOh + o1 + col) = pack2(h2, h3);
            *(uint32_t*)(AOl + o1 + col) = pack2(l2, l3);
        }
    }
}

// ---------------------------------------------------------------------------
// FC GEMM: fp32 out + bias. KD=256.
// ---------------------------------------------------------------------------
__global__ void __launch_bounds__(256, 2) gemm_fc(
    const __nv_bfloat16* __restrict__ Ah, const __nv_bfloat16* __restrict__ Al,
    const __nv_bfloat16* __restrict__ Bh, const __nv_bfloat16* __restrict__ Bl,
    const float* __restrict__ bias, float* __restrict__ Cf)
{
    GEMM_PROLOG
    const int n0 = blockIdx.x * 128, m0 = blockIdx.y * 128;
    const int ma = m0, nb = n0;

    GEMM_MAIN(F_)

    #pragma unroll
    for (int mi = 0; mi < 4; mi++) {
        int r0 = m0 + wm * 64 + mi * 16 + (lane >> 2);
        int r1 = r0 + 8;
        #pragma unroll
        for (int nt = 0; nt < 4; nt++) {
            int col = n0 + wn * 32 + nt * 8 + 2 * lq;
            float b0 = bias[col], b1 = bias[col + 1];
            *(float2*)(Cf + (size_t)r0 * 256 + col) = make_float2(acc[mi][nt][0] + b0, acc[mi][nt][1] + b1);
            *(float2*)(Cf + (size_t)r1 * 256 + col) = make_float2(acc[mi][nt][2] + b0, acc[mi][nt][3] + b1);
        }
    }
}

// ---------------------------------------------------------------------------
extern "C" void kernel_launch(void* const* d_in, const int* in_sizes, int n_in,
                              void* d_out, int out_size)
{
    const float* feat1 = (const float*)d_in[0];
    const float* feat2 = (const float*)d_in[1];
    const float* Wq    = (const float*)d_in[2];
    const float* bq    = (const float*)d_in[3];
    const float* Wk    = (const float*)d_in[4];
    const float* bk    = (const float*)d_in[5];
    const float* Wv    = (const float*)d_in[6];
    const float* bv    = (const float*)d_in[7];
    const float* Wfc   = (const float*)d_in[8];
    const float* bfc   = (const float*)d_in[9];
    float* out = (float*)d_out;

    __nv_bfloat16 *f1h, *f1l, *f2h, *f2l, *Qh, *Ql, *Kh, *Kl, *VTh, *VTl;
    __nv_bfloat16 *Ph, *Pl, *AOh, *AOl;
    float *lp, *lv;
    __nv_bfloat16 (*wq)[D_ * F_]; __nv_bfloat16 (*wk)[D_ * F_];
    __nv_bfloat16 (*wv)[D_ * F_]; __nv_bfloat16 (*wf)[F_ * F_];
    cudaGetSymbolAddress((void**)&f1h, g_f1h);
    cudaGetSymbolAddress((void**)&f1l, g_f1l);
    cudaGetSymbolAddress((void**)&f2h, g_f2h);
    cudaGetSymbolAddress((void**)&f2l, g_f2l);
    cudaGetSymbolAddress((void**)&wq,  g_wq);
    cudaGetSymbolAddress((void**)&wk,  g_wk);
    cudaGetSymbolAddress((void**)&wv,  g_wv);
    cudaGetSymbolAddress((void**)&wf,  g_wf);
    cudaGetSymbolAddress((void**)&Qh,  g_Qh);
    cudaGetSymbolAddress((void**)&Ql,  g_Ql);
    cudaGetSymbolAddress((void**)&Kh,  g_Kh);
    cudaGetSymbolAddress((void**)&Kl,  g_Kl);
    cudaGetSymbolAddress((void**)&VTh, g_VTh);
    cudaGetSymbolAddress((void**)&VTl, g_VTl);
    cudaGetSymbolAddress((void**)&Ph,  g_Ph);
    cudaGetSymbolAddress((void**)&Pl,  g_Pl);
    cudaGetSymbolAddress((void**)&lp,  g_lp);
    cudaGetSymbolAddress((void**)&lv,  g_l);
    cudaGetSymbolAddress((void**)&AOh, g_AOh);
    cudaGetSymbolAddress((void**)&AOl, g_AOl);

    split_f32_kernel<<<NFEAT / 4 / 256, 256>>>(feat1, f1h, f1l, NFEAT / 4);
    split_f32_kernel<<<NFEAT / 4 / 256, 256>>>(feat2, f2h, f2l, NFEAT / 4);
    split_weights_kernel<<<(3 * D_ * F_ + F_ * F_ + 255) / 256, 256>>>(
        Wq, Wk, Wv, Wfc, wq[0], wq[1], wk[0], wk[1], wv[0], wv[1], wf[0], wf[1]);

    cudaFuncSetAttribute(gemm_qkv, cudaFuncAttributeMaxDynamicSharedMemorySize, GEMM_SMEM);
    cudaFuncSetAttribute(gemm_S,   cudaFuncAttributeMaxDynamicSharedMemorySize, GEMM_SMEM);
    cudaFuncSetAttribute(gemm_pv,  cudaFuncAttributeMaxDynamicSharedMemorySize, GEMM_SMEM);
    cudaFuncSetAttribute(gemm_fc,  cudaFuncAttributeMaxDynamicSharedMemorySize, GEMM_SMEM);

    dim3 gq(2, B_ * S1_ / 128, 3);
    gemm_qkv<<<gq, 256, GEMM_SMEM>>>(f1h, f1l, f2h, f2l,
                                     wq[0], wq[1], wk[0], wk[1], wv[0], wv[1],
                                     bq, bk, bv, Qh, Ql, Kh, Kl, VTh, VTl);

    dim3 gs(S2_ / 128, S1_ / 128, B_);     // (16,16,8)
    gemm_S<<<gs, 256, GEMM_SMEM>>>(Qh, Ql, Kh, Kl, Ph, Pl, lp);

    lreduce_kernel<<<(B_ * S1_ + 255) / 256, 256>>>(lp, lv);

    dim3 gp(F_ / 128, S1_ / 128, B_);      // (2,16,8)
    gemm_pv<<<gp, 256, GEMM_SMEM>>>(Ph, Pl, VTh, VTl, lv, AOh, AOl);

    dim3 gg(2, B_ * S1_ / 128);
    gemm_fc<<<gg, 256, GEMM_SMEM>>>(AOh, AOl, wf[0], wf[1], bfc, out);
}